// round 2
// baseline (speedup 1.0000x reference)
#include <cuda_runtime.h>

// Problem: B=16, S=4096.
// predicted_start[b] = argmax_s ( start[b,s] * max_{t>=s} end[b,t] )
// predicted_end[b]   = argmax_t ( end[b,t]   * max_{s<=t} start[b,s] )
// argmax = first occurrence (jnp semantics).

#define SB 16
#define SS 4096
#define NT 1024   // threads per block
#define VPT 4     // elements per thread

__global__ __launch_bounds__(NT, 1)
void probs_to_span_kernel(const float* __restrict__ start_p,
                          const float* __restrict__ end_p,
                          float* __restrict__ out)
{
    const int b   = blockIdx.x;
    const int tid = threadIdx.x;

    const float4* sp = reinterpret_cast<const float4*>(start_p + (size_t)b * SS);
    const float4* ep = reinterpret_cast<const float4*>(end_p   + (size_t)b * SS);

    float4 s4 = sp[tid];
    float4 e4 = ep[tid];
    float st[VPT] = {s4.x, s4.y, s4.z, s4.w};
    float en[VPT] = {e4.x, e4.y, e4.z, e4.w};

    __shared__ float pref[NT];   // chunk maxima of start -> inclusive prefix max
    __shared__ float suff[NT];   // chunk maxima of end   -> inclusive suffix max
    __shared__ int   idx1[NT];
    __shared__ int   idx2[NT];

    const float NEG = -3.0e38f;

    float cs = fmaxf(fmaxf(st[0], st[1]), fmaxf(st[2], st[3]));
    float ce = fmaxf(fmaxf(en[0], en[1]), fmaxf(en[2], en[3]));
    pref[tid] = cs;
    suff[tid] = ce;
    __syncthreads();

    // Fused Hillis-Steele inclusive max-scans: pref forward, suff backward.
    #pragma unroll
    for (int off = 1; off < NT; off <<= 1) {
        float a = (tid >= off)      ? pref[tid - off] : NEG;
        float c = (tid + off < NT)  ? suff[tid + off] : NEG;
        __syncthreads();
        pref[tid] = fmaxf(pref[tid], a);
        suff[tid] = fmaxf(suff[tid], c);
        __syncthreads();
    }

    // Exclusive boundary values for this thread's chunk.
    float pm = (tid > 0)      ? pref[tid - 1] : NEG;   // max start over indices < tid*4
    float sm = (tid < NT - 1) ? suff[tid + 1] : NEG;   // max end   over indices > tid*4+3

    // predicted_end candidate: v2[t] = end[t] * inclusive_prefixmax_start[t]
    // ascending index order, strict '>' keeps first occurrence.
    float bestv2 = NEG; int besti2 = 0;
    float p = pm;
    #pragma unroll
    for (int i = 0; i < VPT; i++) {
        p = fmaxf(p, st[i]);
        float v = en[i] * p;
        if (v > bestv2) { bestv2 = v; besti2 = tid * VPT + i; }
    }

    // predicted_start candidate: v1[s] = start[s] * inclusive_suffixmax_end[s]
    // descending index order, '>=' keeps smallest index among equals.
    float bestv1 = NEG; int besti1 = 0;
    float q = sm;
    #pragma unroll
    for (int i = VPT - 1; i >= 0; i--) {
        q = fmaxf(q, en[i]);
        float v = st[i] * q;
        if (v >= bestv1) { bestv1 = v; besti1 = tid * VPT + i; }
    }

    __syncthreads();   // everyone done reading pref/suff neighbor values

    // Reuse pref/suff as argmax-value arrays.
    pref[tid] = bestv1; idx1[tid] = besti1;
    suff[tid] = bestv2; idx2[tid] = besti2;

    #pragma unroll
    for (int off = NT / 2; off > 0; off >>= 1) {
        __syncthreads();
        if (tid < off) {
            float ov = pref[tid + off]; int oi = idx1[tid + off];
            if (ov > pref[tid] || (ov == pref[tid] && oi < idx1[tid])) {
                pref[tid] = ov; idx1[tid] = oi;
            }
            float ov2 = suff[tid + off]; int oi2 = idx2[tid + off];
            if (ov2 > suff[tid] || (ov2 == suff[tid] && oi2 < idx2[tid])) {
                suff[tid] = ov2; idx2[tid] = oi2;
            }
        }
    }
    __syncthreads();

    if (tid == 0) {
        out[b]      = (float)idx1[0];   // predicted_start
        out[SB + b] = (float)idx2[0];   // predicted_end
    }
}

extern "C" void kernel_launch(void* const* d_in, const int* in_sizes, int n_in,
                              void* d_out, int out_size)
{
    const float* start_p = (const float*)d_in[0];
    const float* end_p   = (const float*)d_in[1];
    float* out           = (float*)d_out;
    probs_to_span_kernel<<<SB, NT>>>(start_p, end_p, out);
}